// round 7
// baseline (speedup 1.0000x reference)
#include <cuda_runtime.h>
#include <cuda_bf16.h>
#include <math_constants.h>
#include <cstdint>

#define BB   16
#define T1C  512
#define T2C  64
#define DC   768
#define HC   12
#define EC   64
#define TKC  576
#define SCALE_P 0.3535533905932738f

// ---------------- scratch ----------------
__device__ float    g_projF[6ULL * BB * T1C * DC];   // tf32-bit floats
__device__ float    g_projI[6ULL * BB * T2C * DC];
__device__ float    g_attV [(size_t)BB * T1C * DC];  // tf32-bit floats
__device__ float    g_attL [(size_t)BB * T2C * DC];
__device__ float    g_maskF[BB * TKC];
__device__ unsigned g_featsT[(size_t)BB * T1C * DC];
__device__ unsigned g_inpsT [(size_t)BB * T2C * DC];
__device__ unsigned g_WfT[6ULL * DC * DC];
__device__ unsigned g_WiT[6ULL * DC * DC];
__device__ unsigned g_WuvT[(size_t)DC * DC];
__device__ unsigned g_WulT[(size_t)DC * DC];

__device__ __forceinline__ unsigned f2tf32(float x)
{ unsigned u; asm("cvt.rna.tf32.f32 %0, %1;" : "=r"(u) : "f"(x)); return u; }

#define MMA_TF32(d, a0, a1, a2, a3, b0, b1)                                   \
    asm volatile("mma.sync.aligned.m16n8k8.row.col.f32.tf32.tf32.f32 "        \
                 "{%0,%1,%2,%3}, {%4,%5,%6,%7}, {%8,%9}, {%0,%1,%2,%3};\n"    \
                 : "+f"(d[0]), "+f"(d[1]), "+f"(d[2]), "+f"(d[3])             \
                 : "r"(a0), "r"(a1), "r"(a2), "r"(a3), "r"(b0), "r"(b1))

__device__ __forceinline__ void cp16(void* dst, const void* src)
{
    unsigned sa = (unsigned)__cvta_generic_to_shared(dst);
    asm volatile("cp.async.ca.shared.global [%0], [%1], 16;" :: "r"(sa), "l"(src));
}
#define CP_COMMIT() asm volatile("cp.async.commit_group;")
template <int N>
__device__ __forceinline__ void cp_wait() { asm volatile("cp.async.wait_group %0;" :: "n"(N)); }

// ---------------- mask prep ----------------
__global__ void mask_prep_kernel(const unsigned* __restrict__ raw, float* __restrict__ mf)
{
    __shared__ int flags[2];
    int tid = threadIdx.x;
    if (tid < 2) flags[tid] = 0;
    __syncthreads();
    int notInt = 0, notU8 = 0;
    const int nWords = (BB * TKC) / 4;
    for (int i = tid; i < nWords; i += blockDim.x) {
        unsigned w = raw[i];
        if (w > 1u) notInt = 1;
        if (w & 0xFEFEFEFEu) notU8 = 1;
    }
    if (notInt) atomicOr(&flags[0], 1);
    if (notU8)  atomicOr(&flags[1], 1);
    __syncthreads();
    int mode = !flags[0] ? 0 : (!flags[1] ? 1 : 2);
    for (int i = tid; i < BB * TKC; i += blockDim.x) {
        float v;
        if (mode == 0)      v = ((const int*)raw)[i] ? 1.f : 0.f;
        else if (mode == 1) v = ((const unsigned char*)raw)[i] ? 1.f : 0.f;
        else                v = (((const float*)raw)[i] != 0.f) ? 1.f : 0.f;
        mf[i] = v;
    }
}

// ---------------- fp32 -> tf32 bits, 6 regions in one launch ----------------
__global__ void cvt6_kernel(
    const float4* s0, uint4* d0, int n0, const float4* s1, uint4* d1, int n1,
    const float4* s2, uint4* d2, int n2, const float4* s3, uint4* d3, int n3,
    const float4* s4, uint4* d4, int n4, const float4* s5, uint4* d5, int n5)
{
    const float4* src; uint4* dst; int n;
    switch (blockIdx.y) {
        case 0: src = s0; dst = d0; n = n0; break;
        case 1: src = s1; dst = d1; n = n1; break;
        case 2: src = s2; dst = d2; n = n2; break;
        case 3: src = s3; dst = d3; n = n3; break;
        case 4: src = s4; dst = d4; n = n4; break;
        default: src = s5; dst = d5; n = n5; break;
    }
    for (int i = blockIdx.x * blockDim.x + threadIdx.x; i < n; i += gridDim.x * blockDim.x) {
        float4 v = src[i];
        uint4 u;
        u.x = f2tf32(v.x); u.y = f2tf32(v.y); u.z = f2tf32(v.z); u.w = f2tf32(v.w);
        dst[i] = u;
    }
}

// ---------------- 3-stage pipelined tf32 GEMM ----------------
// C[z] = (A @ Bw[z] + bias[z]) * scale.  128x128x32 tiles, 256 threads, 8 warps.
#define GA_STR 36
#define GB_STR 136
#define ST_A (128 * GA_STR)
#define ST_B (32 * GB_STR)
#define ST_TOT (ST_A + ST_B)
#define NSTG 3
#define GEMM_SMEM (NSTG * ST_TOT * 4)

__global__ __launch_bounds__(256, 2) void tf32gemm3_kernel(
    const unsigned* __restrict__ A, const unsigned* __restrict__ Bw,
    const float* __restrict__ bias, float* __restrict__ C,
    int M, int N, int K, float scale, int outTf32)
{
    extern __shared__ unsigned sh[];

    const int tid  = threadIdx.x;
    const int wid  = tid >> 5;
    const int lane = tid & 31;
    const int g    = lane >> 2;
    const int tg   = lane & 3;
    const int warpM = (wid & 1) * 64;
    const int warpN = (wid >> 1) * 32;

    const size_t z = blockIdx.z;
    Bw   += z * (size_t)K * N;
    bias += z * (size_t)N;
    C    += z * (size_t)M * N;

    const int rowBase = blockIdx.y * 128;
    const int colBase = blockIdx.x * 128;

    // load mappings
    const int arow = tid >> 1, acol = (tid & 1) * 16;   // A: 2 thr/row, 4x cp16 each
    const int brow = tid >> 3, bcol = (tid & 7) * 16;   // B: 8 thr/row, 4x cp16 each... (16 floats = 4 cp16)

    const unsigned* Ag = A  + (size_t)(rowBase + arow) * K + acol;
    const unsigned* Bg = Bw + (size_t)brow * N + colBase + bcol;

    float acc[4][4][4];
#pragma unroll
    for (int mt = 0; mt < 4; mt++)
#pragma unroll
        for (int nt = 0; nt < 4; nt++)
#pragma unroll
            for (int r = 0; r < 4; r++) acc[mt][nt][r] = 0.f;

    const int NC = K / 32;   // 24

    auto fill = [&](int stage, int c) {
        unsigned* As = sh + stage * ST_TOT;
        unsigned* Bs = As + ST_A;
        const unsigned* As_g = Ag + c * 32;
        const unsigned* Bs_g = Bg + (size_t)c * 32 * N;
        unsigned* Ad = As + arow * GA_STR + acol;
        unsigned* Bd = Bs + brow * GB_STR + bcol;
#pragma unroll
        for (int j = 0; j < 4; j++) cp16(Ad + j * 4, As_g + j * 4);
#pragma unroll
        for (int j = 0; j < 4; j++) cp16(Bd + j * 4, Bs_g + j * 4);
    };

    // prologue: chunks 0,1 into stages 0,1
    fill(0, 0); CP_COMMIT();
    fill(1, 1); CP_COMMIT();

    int stage = 0, nstage = 2 % NSTG;
    for (int c = 0; c < NC; c++) {
        if (c == NC - 1) cp_wait<0>(); else cp_wait<1>();
        __syncthreads();   // chunk c resident + all threads done reading the stage we overwrite next

        if (c + 2 < NC) { fill(nstage, c + 2); CP_COMMIT(); }

        const unsigned* Ab = sh + stage * ST_TOT;
        const unsigned* Bb = Ab + ST_A;
#pragma unroll
        for (int ks = 0; ks < 32; ks += 8) {
            unsigned a[4][4];
#pragma unroll
            for (int mt = 0; mt < 4; mt++) {
                int r0 = warpM + mt * 16 + g;
                a[mt][0] = Ab[r0 * GA_STR + ks + tg];
                a[mt][1] = Ab[(r0 + 8) * GA_STR + ks + tg];
                a[mt][2] = Ab[r0 * GA_STR + ks + tg + 4];
                a[mt][3] = Ab[(r0 + 8) * GA_STR + ks + tg + 4];
            }
            unsigned bf[4][2];
#pragma unroll
            for (int nt = 0; nt < 4; nt++) {
                int c0 = warpN + nt * 8 + g;
                bf[nt][0] = Bb[(ks + tg) * GB_STR + c0];
                bf[nt][1] = Bb[(ks + tg + 4) * GB_STR + c0];
            }
#pragma unroll
            for (int mt = 0; mt < 4; mt++)
#pragma unroll
                for (int nt = 0; nt < 4; nt++)
                    MMA_TF32(acc[mt][nt], a[mt][0], a[mt][1], a[mt][2], a[mt][3],
                             bf[nt][0], bf[nt][1]);
        }
        stage = (stage + 1) % NSTG;
        nstage = (nstage + 1) % NSTG;
    }

    // epilogue
#pragma unroll
    for (int mt = 0; mt < 4; mt++) {
        int row0 = rowBase + warpM + mt * 16 + g;
#pragma unroll
        for (int nt = 0; nt < 4; nt++) {
            int col = colBase + warpN + nt * 8 + 2 * tg;
            float b0 = bias[col], b1 = bias[col + 1];
            float v0 = (acc[mt][nt][0] + b0) * scale;
            float v1 = (acc[mt][nt][1] + b1) * scale;
            float v2 = (acc[mt][nt][2] + b0) * scale;
            float v3 = (acc[mt][nt][3] + b1) * scale;
            if (outTf32) {
                v0 = __uint_as_float(f2tf32(v0));
                v1 = __uint_as_float(f2tf32(v1));
                v2 = __uint_as_float(f2tf32(v2));
                v3 = __uint_as_float(f2tf32(v3));
            }
            *(float2*)(C + (size_t)row0 * N + col)       = make_float2(v0, v1);
            *(float2*)(C + (size_t)(row0 + 8) * N + col) = make_float2(v2, v3);
        }
    }
}

// ---------------- mma-based flash attention (tf32) ----------------
#define APAD 68
#define VPAD 72

__global__ __launch_bounds__(128) void attn_mma_kernel(
    const float* __restrict__ Qa, const float* __restrict__ Qb,
    const float* __restrict__ Kf, const float* __restrict__ Ki,
    const float* __restrict__ Vf, const float* __restrict__ Vi,
    const float* __restrict__ maskF, float* __restrict__ Out, int Tq)
{
    extern __shared__ unsigned smu[];
    unsigned* Qs = smu;
    unsigned* Ks = Qs + 64 * APAD;
    unsigned* Vs = Ks + 64 * APAD;
    unsigned* Ps = Vs + 64 * VPAD;
    float*    Ms = (float*)(Ps + 64 * APAD);

    const int tid = threadIdx.x;
    const int wid = tid >> 5;
    const int g = (tid & 31) >> 2;
    const int tg = tid & 3;
    const int wr = wid * 16;

    const int qt = blockIdx.x, h = blockIdx.y, b = blockIdx.z;
    const int qBase = qt * 64;

    const float* Qa_p = Qa + ((size_t)b * Tq + qBase) * DC + h * EC;
    const float* Qb_p = Qb + ((size_t)b * Tq + qBase) * DC + h * EC;
    const float* Kf_p = Kf + (size_t)b * T1C * DC + h * EC;
    const float* Ki_p = Ki + (size_t)b * T2C * DC + h * EC;
    const float* Vf_p = Vf + (size_t)b * T1C * DC + h * EC;
    const float* Vi_p = Vi + (size_t)b * T2C * DC + h * EC;

    for (int i = tid; i < TKC; i += 128) Ms[i] = maskF[b * TKC + i];

    for (int i = tid; i < 64 * 16; i += 128) {
        int r = i >> 4, c = (i & 15) << 2;
        *(uint4*)&Qs[r * APAD + c] = *(const uint4*)(Qa_p + (size_t)r * DC + c);
    }

    float o[8][4];
#pragma unroll
    for (int et = 0; et < 8; et++)
#pragma unroll
        for (int r = 0; r < 4; r++) o[et][r] = 0.f;
    float mx0 = -CUDART_INF_F, mx1 = -CUDART_INF_F, l0 = 0.f, l1 = 0.f;

    for (int t = 0; t < 9; t++) {
        const float *Kp, *Vp;
        int keyBase;
        if (t < 8) { Kp = Kf_p + (size_t)t * 64 * DC; Vp = Vf_p + (size_t)t * 64 * DC; keyBase = t * 64; }
        else       { Kp = Ki_p;                       Vp = Vi_p;                       keyBase = T1C; }

        __syncthreads();
        if (t == 8) {
            for (int i = tid; i < 64 * 16; i += 128) {
                int r = i >> 4, c = (i & 15) << 2;
                *(uint4*)&Qs[r * APAD + c] = *(const uint4*)(Qb_p + (size_t)r * DC + c);
            }
        }
        for (int i = tid; i < 64 * 16; i += 128) {
            int r = i >> 4, c = (i & 15) << 2;
            *(uint4*)&Ks[r * APAD + c] = *(const uint4*)(Kp + (size_t)r * DC + c);
            *(uint4*)&Vs[r * VPAD + c] = *(const uint4*)(Vp + (size_t)r * DC + c);
        }
        __syncthreads();

        float s[8][4];
#pragma unroll
        for (int nt = 0; nt < 8; nt++)
#pragma unroll
            for (int r = 0; r < 4; r++) s[nt][r] = 0.f;

#pragma unroll
        for (int ks = 0; ks < 64; ks += 8) {
            unsigned a0 = Qs[(wr + g) * APAD + ks + tg];
            unsigned a1 = Qs[(wr + g + 8) * APAD + ks + tg];
            unsigned a2 = Qs[(wr + g) * APAD + ks + tg + 4];
            unsigned a3 = Qs[(wr + g + 8) * APAD + ks + tg + 4];
#pragma unroll
            for (int nt = 0; nt < 8; nt++) {
                unsigned b0 = Ks[(nt * 8 + g) * APAD + ks + tg];
                unsigned b1 = Ks[(nt * 8 + g) * APAD + ks + tg + 4];
                MMA_TF32(s[nt], a0, a1, a2, a3, b0, b1);
            }
        }

        float tm0 = -CUDART_INF_F, tm1 = -CUDART_INF_F;
#pragma unroll
        for (int nt = 0; nt < 8; nt++) {
            float mk0 = Ms[keyBase + nt * 8 + 2 * tg];
            float mk1 = Ms[keyBase + nt * 8 + 2 * tg + 1];
            if (mk0 != 0.f) { s[nt][0] = -1e9f; s[nt][2] = -1e9f; }
            if (mk1 != 0.f) { s[nt][1] = -1e9f; s[nt][3] = -1e9f; }
            tm0 = fmaxf(tm0, fmaxf(s[nt][0], s[nt][1]));
            tm1 = fmaxf(tm1, fmaxf(s[nt][2], s[nt][3]));
        }
        tm0 = fmaxf(tm0, __shfl_xor_sync(0xffffffffu, tm0, 1));
        tm0 = fmaxf(tm0, __shfl_xor_sync(0xffffffffu, tm0, 2));
        tm1 = fmaxf(tm1, __shfl_xor_sync(0xffffffffu, tm1, 1));
        tm1 = fmaxf(tm1, __shfl_xor_sync(0xffffffffu, tm1, 2));

        float mn0 = fmaxf(mx0, tm0), mn1 = fmaxf(mx1, tm1);
        float sc0 = __expf(mx0 - mn0), sc1 = __expf(mx1 - mn1);
        mx0 = mn0; mx1 = mn1;

        float rs0 = 0.f, rs1 = 0.f;
#pragma unroll
        for (int nt = 0; nt < 8; nt++) {
            s[nt][0] = __expf(s[nt][0] - mn0); rs0 += s[nt][0];
            s[nt][1] = __expf(s[nt][1] - mn0); rs0 += s[nt][1];
            s[nt][2] = __expf(s[nt][2] - mn1); rs1 += s[nt][2];
            s[nt][3] = __expf(s[nt][3] - mn1); rs1 += s[nt][3];
        }
        rs0 += __shfl_xor_sync(0xffffffffu, rs0, 1);
        rs0 += __shfl_xor_sync(0xffffffffu, rs0, 2);
        rs1 += __shfl_xor_sync(0xffffffffu, rs1, 1);
        rs1 += __shfl_xor_sync(0xffffffffu, rs1, 2);
        l0 = l0 * sc0 + rs0;
        l1 = l1 * sc1 + rs1;
#pragma unroll
        for (int et = 0; et < 8; et++) {
            o[et][0] *= sc0; o[et][1] *= sc0;
            o[et][2] *= sc1; o[et][3] *= sc1;
        }

#pragma unroll
        for (int nt = 0; nt < 8; nt++) {
            *(uint2*)&Ps[(wr + g) * APAD + nt * 8 + 2 * tg]     = make_uint2(f2tf32(s[nt][0]), f2tf32(s[nt][1]));
            *(uint2*)&Ps[(wr + g + 8) * APAD + nt * 8 + 2 * tg] = make_uint2(f2tf32(s[nt][2]), f2tf32(s[nt][3]));
        }
        __syncwarp();

#pragma unroll
        for (int ks = 0; ks < 64; ks += 8) {
            unsigned a0 = Ps[(wr + g) * APAD + ks + tg];
            unsigned a1 = Ps[(wr + g + 8) * APAD + ks + tg];
            unsigned a2 = Ps[(wr + g) * APAD + ks + tg + 4];
            unsigned a3 = Ps[(wr + g + 8) * APAD + ks + tg + 4];
#pragma unroll
            for (int et = 0; et < 8; et++) {
                unsigned b0 = Vs[(ks + tg) * VPAD + et * 8 + g];
                unsigned b1 = Vs[(ks + tg + 4) * VPAD + et * 8 + g];
                MMA_TF32(o[et], a0, a1, a2, a3, b0, b1);
            }
        }
    }

    // epilogue: normalize, write tf32 bits (feeds tf32 out-proj GEMM)
    float inv0 = 1.f / l0, inv1 = 1.f / l1;
    int r0 = qBase + wr + g;
#pragma unroll
    for (int et = 0; et < 8; et++) {
        int col = h * EC + et * 8 + 2 * tg;
        *(uint2*)(Out + ((size_t)b * Tq + r0) * DC + col) =
            make_uint2(f2tf32(o[et][0] * inv0), f2tf32(o[et][1] * inv0));
        *(uint2*)(Out + ((size_t)b * Tq + r0 + 8) * DC + col) =
            make_uint2(f2tf32(o[et][2] * inv1), f2tf32(o[et][3] * inv1));
    }
}

// ---------------- launch ----------------
extern "C" void kernel_launch(void* const* d_in, const int* in_sizes, int n_in,
                              void* d_out, int out_size)
{
    const float* feats = (const float*)d_in[0];
    const float* inps  = (const float*)d_in[1];
    const void*  amask = d_in[2];
    const float* W_f   = (const float*)d_in[3];
    const float* b_f   = (const float*)d_in[4];
    const float* W_i   = (const float*)d_in[5];
    const float* b_i   = (const float*)d_in[6];
    const float* Wu_v  = (const float*)d_in[7];
    const float* bu_v  = (const float*)d_in[8];
    const float* Wu_l  = (const float*)d_in[9];
    const float* bu_l  = (const float*)d_in[10];
    float* out = (float*)d_out;

    float *projF, *projI, *attV, *attL, *maskF;
    unsigned *featsT, *inpsT, *WfT, *WiT, *WuvT, *WulT;
    cudaGetSymbolAddress((void**)&projF, g_projF);
    cudaGetSymbolAddress((void**)&projI, g_projI);
    cudaGetSymbolAddress((void**)&attV,  g_attV);
    cudaGetSymbolAddress((void**)&attL,  g_attL);
    cudaGetSymbolAddress((void**)&maskF, g_maskF);
    cudaGetSymbolAddress((void**)&featsT, g_featsT);
    cudaGetSymbolAddress((void**)&inpsT,  g_inpsT);
    cudaGetSymbolAddress((void**)&WfT,  g_WfT);
    cudaGetSymbolAddress((void**)&WiT,  g_WiT);
    cudaGetSymbolAddress((void**)&WuvT, g_WuvT);
    cudaGetSymbolAddress((void**)&WulT, g_WulT);

    const size_t SF = (size_t)BB * T1C * DC;
    const size_t SI = (size_t)BB * T2C * DC;
    const int M1 = BB * T1C, M2 = BB * T2C;

    const int attnSmem = (3 * 64 * APAD + 64 * VPAD + TKC) * (int)sizeof(unsigned);
    cudaFuncSetAttribute(tf32gemm3_kernel, cudaFuncAttributeMaxDynamicSharedMemorySize, GEMM_SMEM);
    cudaFuncSetAttribute(attn_mma_kernel,  cudaFuncAttributeMaxDynamicSharedMemorySize, attnSmem);

    // 1) mask + one consolidated cvt pass
    mask_prep_kernel<<<1, 256>>>((const unsigned*)amask, maskF);
    cvt6_kernel<<<dim3(512, 6), 256>>>(
        (const float4*)feats, (uint4*)featsT, (int)(SF / 4),
        (const float4*)inps,  (uint4*)inpsT,  (int)(SI / 4),
        (const float4*)W_f,   (uint4*)WfT,    6 * DC * DC / 4,
        (const float4*)W_i,   (uint4*)WiT,    6 * DC * DC / 4,
        (const float4*)Wu_v,  (uint4*)WuvT,   DC * DC / 4,
        (const float4*)Wu_l,  (uint4*)WulT,   DC * DC / 4);

    // 2) projections (tf32 out), bias + E^-0.25 fused
    tf32gemm3_kernel<<<dim3(DC / 128, M1 / 128, 6), 256, GEMM_SMEM>>>(
        featsT, WfT, b_f, projF, M1, DC, DC, SCALE_P, 1);
    tf32gemm3_kernel<<<dim3(DC / 128, M2 / 128, 6), 256, GEMM_SMEM>>>(
        inpsT, WiT, b_i, projI, M2, DC, DC, SCALE_P, 1);

    // feats stack: [k_vv, q_vv, v_vv, q_lv, k_vl, v_vl]
    // inps  stack: [k_lv, v_lv, q_vl, q_ll, k_ll, v_ll]

    // 3) attention (tf32-bit out)
    attn_mma_kernel<<<dim3(T1C / 64, HC, BB), 128, attnSmem>>>(
        projF + 1 * SF, projF + 3 * SF,
        projF + 0 * SF, projI + 0 * SI,
        projF + 2 * SF, projI + 1 * SI,
        maskF, attV, T1C);
    attn_mma_kernel<<<dim3(T2C / 64, HC, BB), 128, attnSmem>>>(
        projI + 2 * SI, projI + 3 * SI,
        projF + 4 * SF, projI + 4 * SI,
        projF + 5 * SF, projI + 5 * SI,
        maskF, attL, T2C);

    // 4) output projections (fp32 out) into d_out
    tf32gemm3_kernel<<<dim3(DC / 128, M1 / 128, 1), 256, GEMM_SMEM>>>(
        (const unsigned*)attV, WuvT, bu_v, out, M1, DC, DC, 1.0f, 0);
    tf32gemm3_kernel<<<dim3(DC / 128, M2 / 128, 1), 256, GEMM_SMEM>>>(
        (const unsigned*)attL, WulT, bu_l, out + SF, M2, DC, DC, 1.0f, 0);
}